// round 1
// baseline (speedup 1.0000x reference)
#include <cuda_runtime.h>

#define KS   5
#define K2   25      // KS*KS
#define C1   32      // hidden 1
#define C2   64      // hidden 2
#define NG   64      // graphs
#define NMAX 20000

// ---------------- scratch (device globals; no allocations) ----------------
__device__ float g_T[NMAX * K2];          // layer-1 basis-weighted scalar accum
__device__ float g_deg[NMAX];             // in-degree
__device__ float g_h1[NMAX * C1];         // layer-1 output
__device__ float g_S[(long)NMAX * K2 * C1]; // layer-2 basis-weighted feature accum [N][800]  (64MB)
__device__ float g_C[NMAX * C2];          // GEMM output
__device__ float g_pool[NG * C2];
__device__ float g_cnt[NG];

// ---------------- degree-1 B-spline basis (DIM=2, KS=5) ----------------
__device__ __forceinline__ void basis2(float a0, float a1, int* wi, float* bw) {
    float v0 = a0 * (KS - 1), v1 = a1 * (KS - 1);
    int k0 = (int)floorf(v0); k0 = min(max(k0, 0), KS - 2);
    int k1 = (int)floorf(v1); k1 = min(max(k1, 0), KS - 2);
    float f0 = v0 - (float)k0, f1 = v1 - (float)k1;
    float g0 = 1.f - f0, g1 = 1.f - f1;
    wi[0] = k0     + KS *  k1;      bw[0] = g0 * g1;
    wi[1] = k0 + 1 + KS *  k1;      bw[1] = f0 * g1;
    wi[2] = k0     + KS * (k1 + 1); bw[2] = g0 * f1;
    wi[3] = k0 + 1 + KS * (k1 + 1); bw[3] = f0 * f1;
}

// ---------------- zero scratch ----------------
__global__ void k_zero(int N) {
    long tid = (long)blockIdx.x * blockDim.x + threadIdx.x;
    long stride = (long)gridDim.x * blockDim.x;
    long nS4 = (long)N * K2 * C1 / 4;
    float4* S4 = (float4*)g_S;
    float4 z4 = make_float4(0.f, 0.f, 0.f, 0.f);
    for (long i = tid; i < nS4; i += stride) S4[i] = z4;
    long nT = (long)N * K2;
    for (long i = tid; i < nT; i += stride) g_T[i] = 0.f;
    for (long i = tid; i < N; i += stride) g_deg[i] = 0.f;
    for (long i = tid; i < NG * C2; i += stride) g_pool[i] = 0.f;
    for (long i = tid; i < NG; i += stride) g_cnt[i] = 0.f;
}

// ---------------- edge pass 1: T[dst][wi] += b * x[src]; deg ----------------
__global__ void k_edge1(const float* __restrict__ x, const float* __restrict__ ea,
                        const int* __restrict__ src, const int* __restrict__ dst, int E) {
    int e = blockIdx.x * blockDim.x + threadIdx.x;
    if (e >= E) return;
    int wi[4]; float bw[4];
    basis2(ea[2 * e], ea[2 * e + 1], wi, bw);
    float xs = x[src[e]];
    int d = dst[e];
    float* Tp = g_T + d * K2;
#pragma unroll
    for (int i = 0; i < 4; i++) atomicAdd(Tp + wi[i], bw[i] * xs);
    atomicAdd(g_deg + d, 1.f);
}

// ---------------- layer-1 node update: h1 = relu(T@W1/deg + x*root1 + b1) ----------------
__global__ void k_h1(const float* __restrict__ x, const float* __restrict__ W1,
                     const float* __restrict__ root1, const float* __restrict__ b1, int N) {
    int t = blockIdx.x * blockDim.x + threadIdx.x;
    if (t >= N * C1) return;
    int n = t >> 5, c = t & 31;
    const float* Tp = g_T + n * K2;
    float acc = 0.f;
#pragma unroll
    for (int w = 0; w < K2; w++) acc += Tp[w] * W1[w * C1 + c];
    float d = fmaxf(g_deg[n], 1.f);
    float h = acc / d + x[n] * root1[c] + b1[c];
    g_h1[t] = fmaxf(h, 0.f);
}

// ---------------- edge pass 2: S[dst][wi][k] += b * h1[src][k]  (warp/edge) ----------------
__global__ void k_edge2(const float* __restrict__ ea,
                        const int* __restrict__ src, const int* __restrict__ dst, int E) {
    int warp = (blockIdx.x * blockDim.x + threadIdx.x) >> 5;
    int lane = threadIdx.x & 31;
    if (warp >= E) return;
    int s = src[warp], d = dst[warp];
    float hv = g_h1[s * C1 + lane];
    int wi[4]; float bw[4];
    basis2(ea[2 * warp], ea[2 * warp + 1], wi, bw);
    float* Sp = g_S + (long)d * (K2 * C1) + lane;
#pragma unroll
    for (int i = 0; i < 4; i++) atomicAdd(Sp + wi[i] * C1, bw[i] * hv);
}

// ---------------- GEMM: C[N,64] = S[N,800] @ W2[800,64] ----------------
#define BM 128
#define BN 64
#define BK 16
__global__ void k_gemm(const float* __restrict__ W2, int M) {
    __shared__ float As[BM][BK + 1];
    __shared__ float Bs[BK][BN];
    int tid = threadIdx.x;          // 256 threads
    int tx = tid & 15, ty = tid >> 4;
    int rowBase = blockIdx.x * BM;

    float acc[8][4];
#pragma unroll
    for (int i = 0; i < 8; i++)
#pragma unroll
        for (int j = 0; j < 4; j++) acc[i][j] = 0.f;

    for (int kt = 0; kt < K2 * C1; kt += BK) {
        // load A tile: each thread 8 consecutive floats (2x float4)
        int r = tid >> 1;
        int kh = (tid & 1) * 8;
        int grow = rowBase + r;
        if (grow < M) {
            const float* ap = g_S + (long)grow * (K2 * C1) + kt + kh;
            float4 p = *(const float4*)ap;
            float4 q = *(const float4*)(ap + 4);
            As[r][kh + 0] = p.x; As[r][kh + 1] = p.y; As[r][kh + 2] = p.z; As[r][kh + 3] = p.w;
            As[r][kh + 4] = q.x; As[r][kh + 5] = q.y; As[r][kh + 6] = q.z; As[r][kh + 7] = q.w;
        } else {
#pragma unroll
            for (int q = 0; q < 8; q++) As[r][kh + q] = 0.f;
        }
        // load B tile: 1 float4 per thread
        {
            int br = tid >> 4, bc = (tid & 15) * 4;
            float4 b4 = *(const float4*)&W2[(kt + br) * BN + bc];
            *(float4*)&Bs[br][bc] = b4;
        }
        __syncthreads();
#pragma unroll
        for (int kk = 0; kk < BK; kk++) {
            float a[8];
#pragma unroll
            for (int i = 0; i < 8; i++) a[i] = As[ty * 8 + i][kk];
            float4 b4 = *(float4*)&Bs[kk][tx * 4];
            float bb[4] = {b4.x, b4.y, b4.z, b4.w};
#pragma unroll
            for (int i = 0; i < 8; i++)
#pragma unroll
                for (int j = 0; j < 4; j++) acc[i][j] += a[i] * bb[j];
        }
        __syncthreads();
    }
#pragma unroll
    for (int i = 0; i < 8; i++) {
        int grow = rowBase + ty * 8 + i;
        if (grow < M) {
            float4 o = make_float4(acc[i][0], acc[i][1], acc[i][2], acc[i][3]);
            *(float4*)&g_C[grow * C2 + tx * 4] = o;
        }
    }
}

// ---------------- layer-2 node update + graph pooling ----------------
__global__ void k_h2pool(const float* __restrict__ root2, const float* __restrict__ b2,
                         const int* __restrict__ batch, int N) {
    int n = blockIdx.x;
    int o = threadIdx.x;            // 64 threads
    __shared__ float hs[C1];
    if (o < C1) hs[o] = g_h1[n * C1 + o];
    __syncthreads();
    float acc = g_C[n * C2 + o] / fmaxf(g_deg[n], 1.f);
#pragma unroll
    for (int k = 0; k < C1; k++) acc += hs[k] * root2[k * C2 + o];
    acc += b2[o];
    float h = fmaxf(acc, 0.f);
    int b = batch[n];
    atomicAdd(&g_pool[b * C2 + o], h);
    if (o == 0) atomicAdd(&g_cnt[b], 1.f);
}

// ---------------- head MLP + log_softmax (one block per graph) ----------------
__global__ void k_mlp(const float* __restrict__ Wf1, const float* __restrict__ bf1,
                      const float* __restrict__ Wf2, const float* __restrict__ bf2,
                      float* __restrict__ out) {
    int b = blockIdx.x;
    int j = threadIdx.x;            // 128 threads
    __shared__ float gs[C2];
    __shared__ float ts[128];
    __shared__ float lg[10];
    if (j < C2) gs[j] = g_pool[b * C2 + j] / fmaxf(g_cnt[b], 1.f);
    __syncthreads();
    float t = bf1[j];
#pragma unroll
    for (int k = 0; k < C2; k++) t += gs[k] * Wf1[k * 128 + j];
    ts[j] = fmaxf(t, 0.f);
    __syncthreads();
    if (j < 10) {
        float a = bf2[j];
#pragma unroll
        for (int q = 0; q < 128; q++) a += ts[q] * Wf2[q * 10 + j];
        lg[j] = a;
    }
    __syncthreads();
    if (j == 0) {
        float m = lg[0];
#pragma unroll
        for (int q = 1; q < 10; q++) m = fmaxf(m, lg[q]);
        float s = 0.f;
#pragma unroll
        for (int q = 0; q < 10; q++) s += expf(lg[q] - m);
        float l = logf(s) + m;
#pragma unroll
        for (int q = 0; q < 10; q++) out[b * 10 + q] = lg[q] - l;
    }
}

// ---------------- launch ----------------
extern "C" void kernel_launch(void* const* d_in, const int* in_sizes, int n_in,
                              void* d_out, int out_size) {
    const float* x     = (const float*)d_in[0];
    const float* ea    = (const float*)d_in[1];
    const float* W1    = (const float*)d_in[2];
    const float* root1 = (const float*)d_in[3];
    const float* b1    = (const float*)d_in[4];
    const float* W2    = (const float*)d_in[5];
    const float* root2 = (const float*)d_in[6];
    const float* b2    = (const float*)d_in[7];
    const float* Wf1   = (const float*)d_in[8];
    const float* bf1   = (const float*)d_in[9];
    const float* Wf2   = (const float*)d_in[10];
    const float* bf2   = (const float*)d_in[11];
    const int*   ei    = (const int*)d_in[12];
    const int*   batch = (const int*)d_in[13];

    int N = in_sizes[0];        // Cin = 1 -> x has N elements
    int E = in_sizes[1] / 2;    // edge_attr is [E,2]
    const int* src = ei;
    const int* dst = ei + E;
    float* out = (float*)d_out;

    k_zero<<<2048, 256>>>(N);
    k_edge1<<<(E + 255) / 256, 256>>>(x, ea, src, dst, E);
    k_h1<<<(N * C1 + 255) / 256, 256>>>(x, W1, root1, b1, N);
    k_edge2<<<(E + 7) / 8, 256>>>(ea, src, dst, E);
    k_gemm<<<(N + BM - 1) / BM, 256>>>(W2, N);
    k_h2pool<<<N, 64>>>(root2, b2, batch, N);
    k_mlp<<<NG, 128>>>(Wf1, bf1, Wf2, bf2, out);
}